// round 16
// baseline (speedup 1.0000x reference)
#include <cuda_runtime.h>
#include <cuda_bf16.h>

#define BQ 256
#define DD 256
#define NBANK 100000
#define TN 128
#define NUM_TILES ((NBANK + TN - 1) / TN)      // 782
#define NCH 4
#define KCH 64
#define SR 144                                  // smem row stride (128B data + 16B pad)
#define THREADS 512

typedef unsigned long long ull;
typedef unsigned int u32;

// --------------- device scratch --------------------------------------------
__device__ ull    g_aP[BQ];
__device__ ull    g_aF[BQ];
__device__ float  g_a2[BQ];
__device__ int    g_b2maxI;
__device__ uint4  g_Q[NCH][BQ][8];              // hi-split queries (L2-resident)
__device__ float  g_b2[NBANK];
__device__ ull    g_tileP[(size_t)BQ * NUM_TILES];   // [q][tile]
__device__ ull    g_tileF[(size_t)BQ * NUM_TILES];

// --------------- smem layout -------------------------------------------------
#define QBUF  (BQ * SR)                     // 36864
#define BBUF  (TN * SR)                     // 18432
#define OFF_Q    0                          // [2 buf][256][SR]
#define OFF_B    (2 * QBUF)                 // 73728: [2 buf][128][SR]
#define OFF_RED  (OFF_B + 2 * BBUF)         // 110592
#define OFF_B2S  (OFF_RED + 2 * BQ * 8)     // 114688
#define OFF_SCLU (OFF_B2S + 512)
#define OFF_SCLS (OFF_SCLU + 512)
#define OFF_SCID (OFF_SCLS + 512)
#define OFF_SGT  (OFF_SCID + 1024)
#define SMEM_TOTAL (OFF_SGT + 1024)         // 118272

// --------------- helpers -----------------------------------------------------
__device__ __forceinline__ u32 smem_u32(const void* p) {
    u32 a;
    asm("{ .reg .u64 t; cvta.to.shared.u64 t, %1; cvt.u32.u64 %0, t; }" : "=r"(a) : "l"(p));
    return a;
}
#define LDSM_X4(r, addr) \
    asm volatile("ldmatrix.sync.aligned.m8n8.x4.shared.b16 {%0,%1,%2,%3}, [%4];" \
        : "=r"((r)[0]), "=r"((r)[1]), "=r"((r)[2]), "=r"((r)[3]) : "r"(addr))
#define MMA16816(d, a, b0, b1) \
    asm volatile("mma.sync.aligned.m16n8k16.row.col.f32.bf16.bf16.f32 " \
        "{%0,%1,%2,%3}, {%4,%5,%6,%7}, {%8,%9}, {%0,%1,%2,%3};" \
        : "+f"((d)[0]), "+f"((d)[1]), "+f"((d)[2]), "+f"((d)[3]) \
        : "r"((a)[0]), "r"((a)[1]), "r"((a)[2]), "r"((a)[3]), "r"(b0), "r"(b1))
#define CP_ASYNC16(dst, src) \
    asm volatile("cp.async.cg.shared.global [%0], [%1], 16;" :: "r"(dst), "l"(src) : "memory")
#define CP_COMMIT() asm volatile("cp.async.commit_group;" ::: "memory")
#define CP_WAIT0()  asm volatile("cp.async.wait_group 0;" ::: "memory")

__device__ __forceinline__ ull encode(float f, int n) {
    u32 u = __float_as_uint(f);
    u = (u & 0x80000000u) ? ~u : (u | 0x80000000u);
    return ((ull)u << 32) | (u32)n;
}
__device__ __forceinline__ float decode_hi(ull e) {
    u32 u = (u32)(e >> 32);
    u = (u & 0x80000000u) ? (u ^ 0x80000000u) : ~u;
    return __uint_as_float(u);
}
__device__ __forceinline__ u32 hi2(float a0, float a1) {
    __nv_bfloat16 h0 = __float2bfloat16(a0);
    __nv_bfloat16 h1 = __float2bfloat16(a1);
    return (u32)__bfloat16_as_ushort(h0) | ((u32)__bfloat16_as_ushort(h1) << 16);
}

// ---------------------------------------------------------------------------
// prep: one block per query, 128 threads.
// g_Q layout [NCH][BQ][32]u32: chunk = t>>5, word = t&31.
// ---------------------------------------------------------------------------
__global__ void __launch_bounds__(128) prep_kernel(const float* __restrict__ feat) {
    const int q = blockIdx.x, t = threadIdx.x;
    const float2 v = ((const float2*)(feat + (size_t)q * DD))[t];
    ((u32*)g_Q)[(t >> 5) * (BQ * 32) + q * 32 + (t & 31)] = hi2(v.x, v.y);

    float s = fmaf(v.x, v.x, v.y * v.y);
#pragma unroll
    for (int o = 16; o; o >>= 1) s += __shfl_xor_sync(0xffffffffu, s, o);
    __shared__ float ws[4];
    if ((t & 31) == 0) ws[t >> 5] = s;
    __syncthreads();
    if (t == 0) {
        g_a2[q] = ws[0] + ws[1] + ws[2] + ws[3];
        g_aP[q] = ~0ULL;
        g_aF[q] = ~0ULL;
        if (q == 0) g_b2maxI = 0;
    }
}

// ---------------------------------------------------------------------------
__device__ __forceinline__ void stage_q(u32 smb, int buf, int c, int tid) {
#pragma unroll
    for (int p = 0; p < 4; ++p) {              // 2048 pieces / 512 threads
        int idx = tid + THREADS * p;
        int row = idx >> 3, seg = idx & 7;
        CP_ASYNC16(smb + OFF_Q + (u32)buf * QBUF + (u32)row * SR + (u32)seg * 16,
                   &g_Q[c][row][seg]);
    }
}

// Load 16 fp32 (one chunk-quarter of a bank row); zero for pad rows.
__device__ __forceinline__ void ldB(const float* __restrict__ bank, int gn, int c,
                                    int quarter, float4* r) {
    if (gn < NBANK) {
        const float4* p = (const float4*)(bank + (size_t)gn * DD + c * KCH + quarter * 16);
        r[0] = p[0]; r[1] = p[1]; r[2] = p[2]; r[3] = p[3];
    } else {
        r[0] = r[1] = r[2] = r[3] = make_float4(0.f, 0.f, 0.f, 0.f);
    }
}
// Convert 16 fp32 -> bf16, store 32B to smem; return partial square-sum.
__device__ __forceinline__ float cvtB(const float4* r, char* dst) {
    float s = 0.f;
#pragma unroll
    for (int i = 0; i < 4; ++i) {
        s = fmaf(r[i].x, r[i].x, s); s = fmaf(r[i].y, r[i].y, s);
        s = fmaf(r[i].z, r[i].z, s); s = fmaf(r[i].w, r[i].w, s);
    }
    ((uint4*)dst)[0] = make_uint4(hi2(r[0].x, r[0].y), hi2(r[0].z, r[0].w),
                                  hi2(r[1].x, r[1].y), hi2(r[1].z, r[1].w));
    ((uint4*)dst)[1] = make_uint4(hi2(r[2].x, r[2].y), hi2(r[2].z, r[2].w),
                                  hi2(r[3].x, r[3].y), hi2(r[3].z, r[3].w));
    return s;
}

// ---------------------------------------------------------------------------
// Phase A: 512 threads (16 warps), warp tile 32q x 64n, KCH=64 chunks (4
// barriers); fused streaming convert + hi-only bf16 HMMA + masked dual argmin.
// ---------------------------------------------------------------------------
__global__ void __launch_bounds__(THREADS, 1) main_kernel(
    const float* __restrict__ bank,
    const int* __restrict__ cluL, const int* __restrict__ clsL,
    const int* __restrict__ cid,  const int* __restrict__ gt)
{
    extern __shared__ char sm[];
    const u32 smb  = smem_u32(sm);
    const int tid  = threadIdx.x;
    const int lane = tid & 31;
    const int w    = tid >> 5;
    const int n0   = blockIdx.x * TN;

    ull*   redP = (ull*)(sm + OFF_RED);
    ull*   redF = redP + BQ;
    float* b2s  = (float*)(sm + OFF_B2S);
    int*   sClu = (int*)(sm + OFF_SCLU);
    int*   sCls = (int*)(sm + OFF_SCLS);
    int*   sCid = (int*)(sm + OFF_SCID);
    int*   sGt  = (int*)(sm + OFF_SGT);

    // conversion ownership: thread -> (row, 16-float quarter of 64-k chunk)
    const int crow = tid >> 2;
    const int cq   = tid & 3;
    const int cgn  = n0 + crow;
    float b2part = 0.f;

    stage_q(smb, 0, 0, tid);
    CP_COMMIT();
    {
        float4 r[4];
        ldB(bank, cgn, 0, cq, r);
        b2part += cvtB(r, sm + OFF_B + crow * SR + cq * 32);
    }

    if (tid < BQ) {
        redP[tid] = ~0ULL;
        redF[tid] = ~0ULL;
        sCid[tid] = cid[tid];
        sGt[tid]  = gt[tid];
    }
    if (tid < TN) {
        int n = n0 + tid;
        bool v = (n < NBANK);
        sClu[tid] = v ? cluL[n] : -1;
        sCls[tid] = v ? clsL[n] : 0x7fffffff;
    }

    // Warp tiling: 8 q-groups x 2 n-halves. 32q x 64n per warp.
    const int q0 = (w & 7) * 32;
    const int nh = (w >> 3) * 64;

    float acc[2][8][4];
#pragma unroll
    for (int mi = 0; mi < 2; mi++)
#pragma unroll
        for (int nt = 0; nt < 8; nt++)
#pragma unroll
            for (int r = 0; r < 4; r++) acc[mi][nt][r] = 0.f;

    const u32 aRowOff = (u32)(q0 + (lane & 15)) * SR + (u32)(lane >> 4) * 16;
    const int bRow    = nh + ((lane >> 4) & 1) * 8 + (lane & 7);
    const u32 bColB   = ((lane >> 3) & 1) * 16;

    CP_WAIT0();
    __syncthreads();                          // chunk 0 (Q + B) resident

#pragma unroll 1
    for (int c = 0; c < NCH; ++c) {
        float4 pre[4];
        if (c + 1 < NCH) {
            ldB(bank, cgn, c + 1, cq, pre);   // LDGs overlap MMAs below
            stage_q(smb, (c + 1) & 1, c + 1, tid);
            CP_COMMIT();
        }

        const u32 qH  = smb + OFF_Q + (u32)(c & 1) * QBUF + aRowOff;
        const u32 bB0 = smb + OFF_B + (u32)(c & 1) * BBUF;
#pragma unroll
        for (int kk = 0; kk < KCH; kk += 16) {
            const u32 kb = (u32)kk * 2 + bColB;
            u32 aH[2][4];
#pragma unroll
            for (int mi = 0; mi < 2; mi++) LDSM_X4(aH[mi], qH + mi * 16 * SR + kk * 2);
            u32 bB[16];
#pragma unroll
            for (int p = 0; p < 4; p++)
                LDSM_X4(&bB[4 * p], bB0 + (u32)(bRow + p * 16) * SR + kb);
#pragma unroll
            for (int mi = 0; mi < 2; mi++)
#pragma unroll
                for (int nt = 0; nt < 8; nt++)
                    MMA16816(acc[mi][nt], aH[mi], bB[2 * nt], bB[2 * nt + 1]);
        }

        if (c + 1 < NCH)
            b2part += cvtB(pre, sm + OFF_B + ((c + 1) & 1) * BBUF + crow * SR + cq * 32);

        CP_WAIT0();
        __syncthreads();
    }

    // finalize exact b2 per row (reduce across the 4 quarters)
    {
        b2part += __shfl_xor_sync(0xffffffffu, b2part, 1);
        b2part += __shfl_xor_sync(0xffffffffu, b2part, 2);
        if (cq == 0) {
            b2s[crow] = b2part;
            if (cgn < NBANK) {
                g_b2[cgn] = b2part;
                atomicMax(&g_b2maxI, __float_as_int(b2part));
            }
        }
    }
    __syncthreads();

    // ---- epilogue: masked dual argmin from HMMA fragments ----
    {
        const int jb = nh + 2 * (lane & 3);
        float b2r[16]; int clsr[16], clur[16]; bool val[16];
#pragma unroll
        for (int ni = 0; ni < 8; ni++)
#pragma unroll
            for (int h = 0; h < 2; h++) {
                int j = jb + 8 * ni + h, x = ni * 2 + h;
                b2r[x]  = b2s[j];
                clsr[x] = sCls[j];
                clur[x] = sClu[j];
                val[x]  = (n0 + j) < NBANK;
            }
#pragma unroll
        for (int mi = 0; mi < 2; mi++) {
#pragma unroll
            for (int half = 0; half < 2; half++) {
                int r = q0 + mi * 16 + (lane >> 2) + 8 * half;
                int gtq = sGt[r], ciq = sCid[r];
                ull bp = ~0ULL, bf = ~0ULL;
#pragma unroll
                for (int ni = 0; ni < 8; ni++)
#pragma unroll
                    for (int h = 0; h < 2; h++) {
                        int x = ni * 2 + h;
                        if (!val[x] || clsr[x] == gtq) continue;
                        float score = fmaf(-2.f, acc[mi][ni][half * 2 + h], b2r[x]);
                        ull e = encode(score, n0 + jb + 8 * ni + h);
                        if (e < bf) bf = e;
                        if (clur[x] == ciq && e < bp) bp = e;
                    }
#pragma unroll
                for (int o = 1; o <= 2; o <<= 1) {
                    ull tp = __shfl_xor_sync(0xffffffffu, bp, o);
                    ull tf = __shfl_xor_sync(0xffffffffu, bf, o);
                    if (tp < bp) bp = tp;
                    if (tf < bf) bf = tf;
                }
                if ((lane & 3) == 0) {
                    if (bp != ~0ULL) atomicMin(&redP[r], bp);
                    if (bf != ~0ULL) atomicMin(&redF[r], bf);
                }
            }
        }
    }
    __syncthreads();
    if (tid < BQ) {
        ull p = redP[tid], f = redF[tid];
        g_tileP[(size_t)tid * NUM_TILES + blockIdx.x] = p;
        g_tileF[(size_t)tid * NUM_TILES + blockIdx.x] = f;
        if (p != ~0ULL) atomicMin(&g_aP[tid], p);
        if (f != ~0ULL) atomicMin(&g_aF[tid], f);
    }
}

// ---------------------------------------------------------------------------
// Phase B (+gather): one block per query (R14's proven form).
// ---------------------------------------------------------------------------
__global__ void __launch_bounds__(512) rescore_kernel(
    const float* __restrict__ feat, const float* __restrict__ bank,
    const int* __restrict__ cluL, const int* __restrict__ clsL,
    const int* __restrict__ cid,  const int* __restrict__ gt,
    float* __restrict__ out)
{
    __shared__ int   s_tiles[NUM_TILES];
    __shared__ int   s_cnt;
    __shared__ ull   s_best;
    __shared__ float s_thr;
    __shared__ int   s_hasP, s_gt, s_cid;

    const int q    = blockIdx.x;
    const int tid  = threadIdx.x;
    const int lane = tid & 31;
    const int w    = tid >> 5;

    if (tid == 0) {
        s_cnt  = 0;
        s_best = ~0ULL;
        bool hasP = (g_aP[q] != ~0ULL);
        float amin = hasP ? decode_hi(g_aP[q]) : decode_hi(g_aF[q]);
        float m = 0.0078125f * 1.05f * sqrtf(g_a2[q] * __int_as_float(g_b2maxI)) + 0.02f;
        s_thr  = amin + 2.f * m;
        s_hasP = hasP ? 1 : 0;
        s_gt   = gt[q];
        s_cid  = cid[q];
    }
    __syncthreads();

    {
        const ull* tmins = (s_hasP ? g_tileP : g_tileF) + (size_t)q * NUM_TILES;
        for (int t = tid; t < NUM_TILES; t += 512) {
            ull tm = tmins[t];
            if (tm != ~0ULL && decode_hi(tm) <= s_thr) {
                int i = atomicAdd(&s_cnt, 1);
                s_tiles[i] = t;
            }
        }
    }
    __syncthreads();

    const int cnt = s_cnt;
    const float4* fa = (const float4*)(feat + (size_t)q * DD);
    const float4 qa0 = fa[lane * 2], qa1 = fa[lane * 2 + 1];

    for (int i = 0; i < cnt; ++i) {
        const int n0 = s_tiles[i] * TN;
#pragma unroll 1
        for (int r = w; r < TN; r += 16) {
            int n = n0 + r;
            if (n >= NBANK) continue;
            if (clsL[n] == s_gt) continue;
            if (s_hasP && cluL[n] != s_cid) continue;
            const float4* fb = (const float4*)(bank + (size_t)n * DD);
            float4 b0 = fb[lane * 2], b1 = fb[lane * 2 + 1];
            float d = 0.f;
            d = fmaf(qa0.x, b0.x, d); d = fmaf(qa0.y, b0.y, d);
            d = fmaf(qa0.z, b0.z, d); d = fmaf(qa0.w, b0.w, d);
            d = fmaf(qa1.x, b1.x, d); d = fmaf(qa1.y, b1.y, d);
            d = fmaf(qa1.z, b1.z, d); d = fmaf(qa1.w, b1.w, d);
#pragma unroll
            for (int o = 16; o; o >>= 1) d += __shfl_xor_sync(0xffffffffu, d, o);
            if (lane == 0)
                atomicMin(&s_best, encode(fmaf(-2.f, d, g_b2[n]), n));
        }
    }
    __syncthreads();

    {
        ull e = s_best;
        int idx = (e == ~0ULL) ? 0 : (int)(u32)(e & 0xffffffffu);
        if (tid < 64) {
            const float4* src = (const float4*)(bank + (size_t)idx * DD);
            float4*       dst = (float4*)(out + (size_t)q * DD);
            dst[tid] = src[tid];
        }
    }
}

// ---------------------------------------------------------------------------
extern "C" void kernel_launch(void* const* d_in, const int* in_sizes, int n_in,
                              void* d_out, int out_size) {
    const float* feature = (const float*)d_in[0];
    const float* bank    = (const float*)d_in[1];
    const int*   cluL    = (const int*)d_in[2];
    const int*   clsL    = (const int*)d_in[3];
    const int*   cid     = (const int*)d_in[4];
    const int*   gtl     = (const int*)d_in[5];

    cudaFuncSetAttribute(main_kernel,
                         cudaFuncAttributeMaxDynamicSharedMemorySize, SMEM_TOTAL);

    prep_kernel<<<BQ, 128>>>(feature);                                           // #1
    main_kernel<<<NUM_TILES, THREADS, SMEM_TOTAL>>>(bank, cluL, clsL, cid, gtl); // #2
    rescore_kernel<<<BQ, 512>>>(feature, bank, cluL, clsL, cid, gtl,
                                (float*)d_out);                                  // #3
}

// round 17
// speedup vs baseline: 1.2816x; 1.2816x over previous
#include <cuda_runtime.h>
#include <cuda_bf16.h>

#define BQ 256
#define DD 256
#define NBANK 100000
#define TN 128
#define NUM_TILES ((NBANK + TN - 1) / TN)      // 782
#define NCH 8
#define KCH 32
#define SR 80                                   // smem row stride (64B data + 16B pad)
#define THREADS 512

typedef unsigned long long ull;
typedef unsigned int u32;

// --------------- device scratch --------------------------------------------
__device__ ull    g_aP[BQ];
__device__ ull    g_aF[BQ];
__device__ float  g_a2[BQ];
__device__ int    g_b2maxI;
__device__ uint4  g_Q[NCH][BQ][4];              // hi-split queries (L2-resident)
__device__ float  g_b2[NBANK];
__device__ ull    g_tileP[(size_t)BQ * NUM_TILES];   // [q][tile]
__device__ ull    g_tileF[(size_t)BQ * NUM_TILES];

// --------------- smem layout -------------------------------------------------
#define QBUF  (BQ * SR)                     // 20480
#define BBUF  (TN * SR)                     // 10240
#define OFF_Q    0                          // [2 buf][256][SR]
#define OFF_B    (2 * QBUF)                 // 40960: [2 buf][128][SR]
#define OFF_RED  (OFF_B + 2 * BBUF)         // 61440
#define OFF_B2S  (OFF_RED + 2 * BQ * 8)     // 65536
#define OFF_SCLU (OFF_B2S + 512)
#define OFF_SCLS (OFF_SCLU + 512)
#define OFF_SCID (OFF_SCLS + 512)
#define OFF_SGT  (OFF_SCID + 1024)
#define SMEM_TOTAL (OFF_SGT + 1024)         // 69120

// --------------- helpers -----------------------------------------------------
__device__ __forceinline__ u32 smem_u32(const void* p) {
    u32 a;
    asm("{ .reg .u64 t; cvta.to.shared.u64 t, %1; cvt.u32.u64 %0, t; }" : "=r"(a) : "l"(p));
    return a;
}
#define LDSM_X4(r, addr) \
    asm volatile("ldmatrix.sync.aligned.m8n8.x4.shared.b16 {%0,%1,%2,%3}, [%4];" \
        : "=r"((r)[0]), "=r"((r)[1]), "=r"((r)[2]), "=r"((r)[3]) : "r"(addr))
#define MMA16816(d, a, b0, b1) \
    asm volatile("mma.sync.aligned.m16n8k16.row.col.f32.bf16.bf16.f32 " \
        "{%0,%1,%2,%3}, {%4,%5,%6,%7}, {%8,%9}, {%0,%1,%2,%3};" \
        : "+f"((d)[0]), "+f"((d)[1]), "+f"((d)[2]), "+f"((d)[3]) \
        : "r"((a)[0]), "r"((a)[1]), "r"((a)[2]), "r"((a)[3]), "r"(b0), "r"(b1))
#define CP_ASYNC16(dst, src) \
    asm volatile("cp.async.cg.shared.global [%0], [%1], 16;" :: "r"(dst), "l"(src) : "memory")
#define CP_COMMIT() asm volatile("cp.async.commit_group;" ::: "memory")
#define CP_WAIT0()  asm volatile("cp.async.wait_group 0;" ::: "memory")

__device__ __forceinline__ ull encode(float f, int n) {
    u32 u = __float_as_uint(f);
    u = (u & 0x80000000u) ? ~u : (u | 0x80000000u);
    return ((ull)u << 32) | (u32)n;
}
__device__ __forceinline__ float decode_hi(ull e) {
    u32 u = (u32)(e >> 32);
    u = (u & 0x80000000u) ? (u ^ 0x80000000u) : ~u;
    return __uint_as_float(u);
}
__device__ __forceinline__ u32 hi2(float a0, float a1) {
    __nv_bfloat16 h0 = __float2bfloat16(a0);
    __nv_bfloat16 h1 = __float2bfloat16(a1);
    return (u32)__bfloat16_as_ushort(h0) | ((u32)__bfloat16_as_ushort(h1) << 16);
}

// ---------------------------------------------------------------------------
// prep: one block per query, 128 threads.
// ---------------------------------------------------------------------------
__global__ void __launch_bounds__(128) prep_kernel(const float* __restrict__ feat) {
    const int q = blockIdx.x, t = threadIdx.x;
    const float2 v = ((const float2*)(feat + (size_t)q * DD))[t];
    ((u32*)g_Q)[(t >> 4) * (BQ * 16) + q * 16 + (t & 15)] = hi2(v.x, v.y);

    float s = fmaf(v.x, v.x, v.y * v.y);
#pragma unroll
    for (int o = 16; o; o >>= 1) s += __shfl_xor_sync(0xffffffffu, s, o);
    __shared__ float ws[4];
    if ((t & 31) == 0) ws[t >> 5] = s;
    __syncthreads();
    if (t == 0) {
        g_a2[q] = ws[0] + ws[1] + ws[2] + ws[3];
        g_aP[q] = ~0ULL;
        g_aF[q] = ~0ULL;
        if (q == 0) g_b2maxI = 0;
    }
}

// ---------------------------------------------------------------------------
__device__ __forceinline__ void stage_q(u32 smb, int buf, int c, int tid) {
#pragma unroll
    for (int p = 0; p < 2; ++p) {              // 1024 pieces / 512 threads
        int idx = tid + THREADS * p;
        int row = idx >> 2, seg = idx & 3;
        CP_ASYNC16(smb + OFF_Q + (u32)buf * QBUF + (u32)row * SR + (u32)seg * 16,
                   &g_Q[c][row][seg]);
    }
}

// Load 8 fp32 (one chunk-quarter of a bank row); zero for pad rows.
__device__ __forceinline__ void ldB(const float* __restrict__ bank, int gn, int c,
                                    int quarter, float4* r) {
    if (gn < NBANK) {
        const float4* p = (const float4*)(bank + (size_t)gn * DD + c * KCH + quarter * 8);
        r[0] = p[0]; r[1] = p[1];
    } else {
        r[0] = r[1] = make_float4(0.f, 0.f, 0.f, 0.f);
    }
}
// Convert 8 fp32 -> bf16, store 16B to smem; return partial square-sum.
__device__ __forceinline__ float cvtB(const float4* r, char* dst) {
    float s = 0.f;
#pragma unroll
    for (int i = 0; i < 2; ++i) {
        s = fmaf(r[i].x, r[i].x, s); s = fmaf(r[i].y, r[i].y, s);
        s = fmaf(r[i].z, r[i].z, s); s = fmaf(r[i].w, r[i].w, s);
    }
    *(uint4*)dst = make_uint4(hi2(r[0].x, r[0].y), hi2(r[0].z, r[0].w),
                              hi2(r[1].x, r[1].y), hi2(r[1].z, r[1].w));
    return s;
}

// ---------------------------------------------------------------------------
// Phase A: 512 threads (16 warps), warp tile 32q x 64n; fused streaming
// convert + hi-only bf16 HMMA GEMM + masked dual argmin. (R14 + A-LDSM hoist.)
// ---------------------------------------------------------------------------
__global__ void __launch_bounds__(THREADS, 1) main_kernel(
    const float* __restrict__ bank,
    const int* __restrict__ cluL, const int* __restrict__ clsL,
    const int* __restrict__ cid,  const int* __restrict__ gt)
{
    extern __shared__ char sm[];
    const u32 smb  = smem_u32(sm);
    const int tid  = threadIdx.x;
    const int lane = tid & 31;
    const int w    = tid >> 5;
    const int n0   = blockIdx.x * TN;

    ull*   redP = (ull*)(sm + OFF_RED);
    ull*   redF = redP + BQ;
    float* b2s  = (float*)(sm + OFF_B2S);
    int*   sClu = (int*)(sm + OFF_SCLU);
    int*   sCls = (int*)(sm + OFF_SCLS);
    int*   sCid = (int*)(sm + OFF_SCID);
    int*   sGt  = (int*)(sm + OFF_SGT);

    const int crow = tid >> 2;
    const int cq   = tid & 3;
    const int cgn  = n0 + crow;
    float b2part = 0.f;

    stage_q(smb, 0, 0, tid);
    CP_COMMIT();
    {
        float4 r[2];
        ldB(bank, cgn, 0, cq, r);
        b2part += cvtB(r, sm + OFF_B + crow * SR + cq * 16);
    }

    if (tid < BQ) {
        redP[tid] = ~0ULL;
        redF[tid] = ~0ULL;
        sCid[tid] = cid[tid];
        sGt[tid]  = gt[tid];
    }
    if (tid < TN) {
        int n = n0 + tid;
        bool v = (n < NBANK);
        sClu[tid] = v ? cluL[n] : -1;
        sCls[tid] = v ? clsL[n] : 0x7fffffff;
    }

    const int q0 = (w & 7) * 32;
    const int nh = (w >> 3) * 64;

    float acc[2][8][4];
#pragma unroll
    for (int mi = 0; mi < 2; mi++)
#pragma unroll
        for (int nt = 0; nt < 8; nt++)
#pragma unroll
            for (int r = 0; r < 4; r++) acc[mi][nt][r] = 0.f;

    const u32 aRowOff = (u32)(q0 + (lane & 15)) * SR + (u32)(lane >> 4) * 16;
    const int bRow    = nh + ((lane >> 4) & 1) * 8 + (lane & 7);
    const u32 bColB   = ((lane >> 3) & 1) * 16;

    CP_WAIT0();
    __syncthreads();                          // chunk 0 (Q + B) resident

#pragma unroll 1
    for (int c = 0; c < NCH; ++c) {
        float4 pre[2];
        if (c + 1 < NCH) {
            ldB(bank, cgn, c + 1, cq, pre);   // LDGs overlap MMAs below
            stage_q(smb, (c + 1) & 1, c + 1, tid);
            CP_COMMIT();
        }

        const u32 qH  = smb + OFF_Q + (u32)(c & 1) * QBUF + aRowOff;
        const u32 bB0 = smb + OFF_B + (u32)(c & 1) * BBUF;

        // Hoist ALL A fragments for the chunk (both kk steps) before the MMAs.
        u32 aH[2][2][4];
#pragma unroll
        for (int ks = 0; ks < 2; ks++)
#pragma unroll
            for (int mi = 0; mi < 2; mi++)
                LDSM_X4(aH[ks][mi], qH + mi * 16 * SR + ks * 32);

#pragma unroll
        for (int ks = 0; ks < 2; ks++) {
            const u32 kb = (u32)ks * 32 + bColB;
            u32 bB[16];
#pragma unroll
            for (int p = 0; p < 4; p++)
                LDSM_X4(&bB[4 * p], bB0 + (u32)(bRow + p * 16) * SR + kb);
#pragma unroll
            for (int mi = 0; mi < 2; mi++)
#pragma unroll
                for (int nt = 0; nt < 8; nt++)
                    MMA16816(acc[mi][nt], aH[ks][mi], bB[2 * nt], bB[2 * nt + 1]);
        }

        if (c + 1 < NCH)
            b2part += cvtB(pre, sm + OFF_B + ((c + 1) & 1) * BBUF + crow * SR + cq * 16);

        CP_WAIT0();
        __syncthreads();
    }

    // finalize exact b2 per row (reduce across the 4 quarters)
    {
        b2part += __shfl_xor_sync(0xffffffffu, b2part, 1);
        b2part += __shfl_xor_sync(0xffffffffu, b2part, 2);
        if (cq == 0) {
            b2s[crow] = b2part;
            if (cgn < NBANK) {
                g_b2[cgn] = b2part;
                atomicMax(&g_b2maxI, __float_as_int(b2part));
            }
        }
    }
    __syncthreads();

    // ---- epilogue: masked dual argmin from HMMA fragments ----
    {
        const int jb = nh + 2 * (lane & 3);
        float b2r[16]; int clsr[16], clur[16]; bool val[16];
#pragma unroll
        for (int ni = 0; ni < 8; ni++)
#pragma unroll
            for (int h = 0; h < 2; h++) {
                int j = jb + 8 * ni + h, x = ni * 2 + h;
                b2r[x]  = b2s[j];
                clsr[x] = sCls[j];
                clur[x] = sClu[j];
                val[x]  = (n0 + j) < NBANK;
            }
#pragma unroll
        for (int mi = 0; mi < 2; mi++) {
#pragma unroll
            for (int half = 0; half < 2; half++) {
                int r = q0 + mi * 16 + (lane >> 2) + 8 * half;
                int gtq = sGt[r], ciq = sCid[r];
                ull bp = ~0ULL, bf = ~0ULL;
#pragma unroll
                for (int ni = 0; ni < 8; ni++)
#pragma unroll
                    for (int h = 0; h < 2; h++) {
                        int x = ni * 2 + h;
                        if (!val[x] || clsr[x] == gtq) continue;
                        float score = fmaf(-2.f, acc[mi][ni][half * 2 + h], b2r[x]);
                        ull e = encode(score, n0 + jb + 8 * ni + h);
                        if (e < bf) bf = e;
                        if (clur[x] == ciq && e < bp) bp = e;
                    }
#pragma unroll
                for (int o = 1; o <= 2; o <<= 1) {
                    ull tp = __shfl_xor_sync(0xffffffffu, bp, o);
                    ull tf = __shfl_xor_sync(0xffffffffu, bf, o);
                    if (tp < bp) bp = tp;
                    if (tf < bf) bf = tf;
                }
                if ((lane & 3) == 0) {
                    if (bp != ~0ULL) atomicMin(&redP[r], bp);
                    if (bf != ~0ULL) atomicMin(&redF[r], bf);
                }
            }
        }
    }
    __syncthreads();
    if (tid < BQ) {
        ull p = redP[tid], f = redF[tid];
        g_tileP[(size_t)tid * NUM_TILES + blockIdx.x] = p;
        g_tileF[(size_t)tid * NUM_TILES + blockIdx.x] = f;
        if (p != ~0ULL) atomicMin(&g_aP[tid], p);
        if (f != ~0ULL) atomicMin(&g_aF[tid], f);
    }
}

// ---------------------------------------------------------------------------
// Phase B (+gather): one block per query (R14's proven form).
// ---------------------------------------------------------------------------
__global__ void __launch_bounds__(512) rescore_kernel(
    const float* __restrict__ feat, const float* __restrict__ bank,
    const int* __restrict__ cluL, const int* __restrict__ clsL,
    const int* __restrict__ cid,  const int* __restrict__ gt,
    float* __restrict__ out)
{
    __shared__ int   s_tiles[NUM_TILES];
    __shared__ int   s_cnt;
    __shared__ ull   s_best;
    __shared__ float s_thr;
    __shared__ int   s_hasP, s_gt, s_cid;

    const int q    = blockIdx.x;
    const int tid  = threadIdx.x;
    const int lane = tid & 31;
    const int w    = tid >> 5;

    if (tid == 0) {
        s_cnt  = 0;
        s_best = ~0ULL;
        bool hasP = (g_aP[q] != ~0ULL);
        float amin = hasP ? decode_hi(g_aP[q]) : decode_hi(g_aF[q]);
        float m = 0.0078125f * 1.05f * sqrtf(g_a2[q] * __int_as_float(g_b2maxI)) + 0.02f;
        s_thr  = amin + 2.f * m;
        s_hasP = hasP ? 1 : 0;
        s_gt   = gt[q];
        s_cid  = cid[q];
    }
    __syncthreads();

    {
        const ull* tmins = (s_hasP ? g_tileP : g_tileF) + (size_t)q * NUM_TILES;
        for (int t = tid; t < NUM_TILES; t += 512) {
            ull tm = tmins[t];
            if (tm != ~0ULL && decode_hi(tm) <= s_thr) {
                int i = atomicAdd(&s_cnt, 1);
                s_tiles[i] = t;
            }
        }
    }
    __syncthreads();

    const int cnt = s_cnt;
    const float4* fa = (const float4*)(feat + (size_t)q * DD);
    const float4 qa0 = fa[lane * 2], qa1 = fa[lane * 2 + 1];

    for (int i = 0; i < cnt; ++i) {
        const int n0 = s_tiles[i] * TN;
#pragma unroll 1
        for (int r = w; r < TN; r += 16) {
            int n = n0 + r;
            if (n >= NBANK) continue;
            if (clsL[n] == s_gt) continue;
            if (s_hasP && cluL[n] != s_cid) continue;
            const float4* fb = (const float4*)(bank + (size_t)n * DD);
            float4 b0 = fb[lane * 2], b1 = fb[lane * 2 + 1];
            float d = 0.f;
            d = fmaf(qa0.x, b0.x, d); d = fmaf(qa0.y, b0.y, d);
            d = fmaf(qa0.z, b0.z, d); d = fmaf(qa0.w, b0.w, d);
            d = fmaf(qa1.x, b1.x, d); d = fmaf(qa1.y, b1.y, d);
            d = fmaf(qa1.z, b1.z, d); d = fmaf(qa1.w, b1.w, d);
#pragma unroll
            for (int o = 16; o; o >>= 1) d += __shfl_xor_sync(0xffffffffu, d, o);
            if (lane == 0)
                atomicMin(&s_best, encode(fmaf(-2.f, d, g_b2[n]), n));
        }
    }
    __syncthreads();

    {
        ull e = s_best;
        int idx = (e == ~0ULL) ? 0 : (int)(u32)(e & 0xffffffffu);
        if (tid < 64) {
            const float4* src = (const float4*)(bank + (size_t)idx * DD);
            float4*       dst = (float4*)(out + (size_t)q * DD);
            dst[tid] = src[tid];
        }
    }
}

// ---------------------------------------------------------------------------
extern "C" void kernel_launch(void* const* d_in, const int* in_sizes, int n_in,
                              void* d_out, int out_size) {
    const float* feature = (const float*)d_in[0];
    const float* bank    = (const float*)d_in[1];
    const int*   cluL    = (const int*)d_in[2];
    const int*   clsL    = (const int*)d_in[3];
    const int*   cid     = (const int*)d_in[4];
    const int*   gtl     = (const int*)d_in[5];

    cudaFuncSetAttribute(main_kernel,
                         cudaFuncAttributeMaxDynamicSharedMemorySize, SMEM_TOTAL);

    prep_kernel<<<BQ, 128>>>(feature);                                           // #1
    main_kernel<<<NUM_TILES, THREADS, SMEM_TOTAL>>>(bank, cluL, clsL, cid, gtl); // #2
    rescore_kernel<<<BQ, 512>>>(feature, bank, cluL, clsL, cid, gtl,
                                (float*)d_out);                                  // #3
}